// round 3
// baseline (speedup 1.0000x reference)
#include <cuda_runtime.h>
#include <cstdint>

// ---------------------------------------------------------------------------
// BiLSTM: B=128, S=1024, D=128, H=256.
// concat[b,k] = x[k,t,b] (k<128)  |  h[b,k-128]  (source transpose quirk, B==D)
// z[g,row,b] = sum_k W[g,row,k]*concat[b,k] + bias[g,row]; gates f,i,c~,o.
//
// Parallel decomposition:
//   16 clusters x 8 CTAs (128 CTAs, 1 CTA/SM, 229 KB smem each).
//   cluster -> (direction, 16-batch group). CTA rank -> 32-hidden-unit slice
//   (128 gate rows of W, 384 cols, resident in SMEM = 192 KB, loaded once).
//   Per step: GEMM  z[128 x 16] = Wslice[128 x 384] @ concat[384 x 16]
//   using fma.rn.f32x2 (packed row-pairs) -> 128 FMA/SM/cyc.
//   h_next slices broadcast cluster-wide via st.shared::cluster (DSMEM),
//   two barrier.cluster per step for producer/consumer ordering.
// ---------------------------------------------------------------------------

namespace {
constexpr int Bsz = 128, Ssz = 1024, Dsz = 128, Hsz = 256, Ksz = 384;
constexpr int NB  = 16;    // batches per cluster
constexpr int CL  = 8;     // CTAs per cluster
constexpr int RWS = 128;   // gate rows per CTA (4 gates x 32 hidden)
constexpr int JSL = 32;    // hidden units per CTA

constexpr int W_ELE = Ksz * RWS;   // 49152 floats (192 KB)
constexpr int C_ELE = Ksz * NB;    // 6144  floats (24 KB)  concat buffer
constexpr int Z_ELE = RWS * NB;    // 2048  floats (8 KB)   gate preacts
constexpr int SMEM_BYTES = (W_ELE + C_ELE + Z_ELE) * 4;  // 229376 B

constexpr long long OUT_MAIN = (long long)Bsz * Ssz * 2 * Hsz;   // 67108864
constexpr long long OUT_FULL = OUT_MAIN + 4LL * Bsz * Hsz;       // 67239936
}

__device__ __forceinline__ uint32_t smem_u32(const void* p) {
    uint32_t a;
    asm("{ .reg .u64 t; cvta.to.shared.u64 t, %1; cvt.u32.u64 %0, t; }"
        : "=r"(a) : "l"(p));
    return a;
}

// Accurate fast activations (MUFU-based exp, IEEE divide): abs err ~1e-7.
__device__ __forceinline__ float sigm(float v)  { return 1.0f / (1.0f + __expf(-v)); }
__device__ __forceinline__ float tanhf_(float v){ return 1.0f - 2.0f / (__expf(2.0f * v) + 1.0f); }

#define CLUSTER_SYNC() do {                                            \
    asm volatile("barrier.cluster.arrive.aligned;" ::: "memory");      \
    asm volatile("barrier.cluster.wait.aligned;"   ::: "memory");      \
} while (0)

__global__ void __launch_bounds__(256, 1) __cluster_dims__(CL, 1, 1)
bilstm_kernel(const float* __restrict__ x,
              const float* __restrict__ Wf, const float* __restrict__ bf,
              const float* __restrict__ Wb, const float* __restrict__ bb,
              float* __restrict__ out, int write_states)
{
    extern __shared__ float sm[];
    float* Wsm  = sm;              // [k][128]  k-major so 4 consecutive rows = LDS.128
    float* cbuf = sm + W_ELE;      // [k][16]   k<128: x-part, k>=128: h-part
    float* zbuf = cbuf + C_ELE;    // [row][16]

    const int tid  = threadIdx.x;
    const int rank = blockIdx.x & 7;        // CTA rank in cluster
    const int cid  = blockIdx.x >> 3;       // cluster id (0..15)
    const int dir  = cid >> 3;              // 0 = fwd, 1 = bwd
    const int bg   = (cid & 7) * NB;        // first batch of this cluster

    const float* W    = dir ? Wb : Wf;
    const float* bias = dir ? bb : bf;

    // --- load resident weight slice (coalesced on gmem, once) ---
    for (int i = tid; i < RWS * Ksz; i += 256) {
        int r = i / Ksz, k = i - r * Ksz;
        int g = r >> 5, jl = r & 31;
        Wsm[k * RWS + r] = W[(g * Hsz + rank * JSL + jl) * Ksz + k];
    }
    // h := 0
    for (int i = tid; i < Hsz * NB; i += 256) cbuf[Dsz * NB + i] = 0.f;

    // x slice for step 0: cbuf[k][b] = x[k, tt0, bg+b]
    const int prow = tid >> 1, pq = (tid & 1) * 8;
    {
        int tt0 = dir ? (Ssz - 1) : 0;
        const float4* src = (const float4*)(x + (size_t)prow * Ssz * Dsz
                                              + (size_t)tt0 * Dsz + bg + pq);
        float4 v0 = src[0], v1 = src[1];
        *(float4*)(cbuf + prow * NB + pq)     = v0;
        *(float4*)(cbuf + prow * NB + pq + 4) = v1;
    }

    // thread tiling: rows 4*rg..4*rg+3  x  cols 2*cg..2*cg+1
    const int rg = tid >> 3;            // 0..31 (doubles as hidden idx j in epilogue)
    const int cg = tid & 7;             // 0..7
    const int hg = rank * JSL + rg;     // global hidden unit this thread finalizes
    const float bsf = bias[0 * Hsz + hg], bsi = bias[1 * Hsz + hg],
                bsc = bias[2 * Hsz + hg], bso = bias[3 * Hsz + hg];

    const uint32_t smb   = smem_u32(sm);
    const uint32_t wA    = smb + rg * 16;                                  // + k*512
    const uint32_t cA    = smb + (uint32_t)W_ELE * 4 + cg * 8;             // + k*64
    const uint32_t haddr = smb + (uint32_t)(W_ELE + (Dsz + hg) * NB) * 4 + cg * 8;

    float c0s = 0.f, c1s = 0.f;   // cell state for (hg, b0) and (hg, b0+1)

    __syncthreads();

    for (int step = 0; step < Ssz; ++step) {
        const int  tt = dir ? (Ssz - 1 - step) : step;
        const bool pf = (step + 1 < Ssz);

        // prefetch next timestep's x slice into registers (covers DRAM latency)
        float4 p0, p1;
        if (pf) {
            const int ttn = dir ? (tt - 1) : (tt + 1);
            const float4* src = (const float4*)(x + (size_t)prow * Ssz * Dsz
                                                  + (size_t)ttn * Dsz + bg + pq);
            p0 = src[0]; p1 = src[1];
        }

        // ---- GEMM: 4 packed f32x2 accumulators (2 row-pairs x 2 cols) ----
        unsigned long long a0 = 0ull, a1 = 0ull, a2 = 0ull, a3 = 0ull;
        uint32_t wa = wA, ca = cA;
        #pragma unroll 8
        for (int k = 0; k < Ksz; ++k) {
            unsigned long long w01, w23;
            float cv0, cv1;
            asm volatile("ld.shared.v2.u64 {%0,%1},[%2];"
                         : "=l"(w01), "=l"(w23) : "r"(wa));
            asm volatile("ld.shared.v2.f32 {%0,%1},[%2];"
                         : "=f"(cv0), "=f"(cv1) : "r"(ca));
            unsigned long long cc0, cc1;
            uint32_t u0 = __float_as_uint(cv0), u1 = __float_as_uint(cv1);
            asm("mov.b64 %0,{%1,%1};" : "=l"(cc0) : "r"(u0));
            asm("mov.b64 %0,{%1,%1};" : "=l"(cc1) : "r"(u1));
            asm("fma.rn.f32x2 %0,%1,%2,%0;" : "+l"(a0) : "l"(w01), "l"(cc0));
            asm("fma.rn.f32x2 %0,%1,%2,%0;" : "+l"(a1) : "l"(w23), "l"(cc0));
            asm("fma.rn.f32x2 %0,%1,%2,%0;" : "+l"(a2) : "l"(w01), "l"(cc1));
            asm("fma.rn.f32x2 %0,%1,%2,%0;" : "+l"(a3) : "l"(w23), "l"(cc1));
            wa += RWS * 4; ca += NB * 4;
        }

        // unpack accumulators, stage z in smem
        float a0l, a0h, a1l, a1h, a2l, a2h, a3l, a3h;
        {
            uint32_t lo, hi;
            asm("mov.b64 {%0,%1},%2;" : "=r"(lo), "=r"(hi) : "l"(a0));
            a0l = __uint_as_float(lo); a0h = __uint_as_float(hi);
            asm("mov.b64 {%0,%1},%2;" : "=r"(lo), "=r"(hi) : "l"(a1));
            a1l = __uint_as_float(lo); a1h = __uint_as_float(hi);
            asm("mov.b64 {%0,%1},%2;" : "=r"(lo), "=r"(hi) : "l"(a2));
            a2l = __uint_as_float(lo); a2h = __uint_as_float(hi);
            asm("mov.b64 {%0,%1},%2;" : "=r"(lo), "=r"(hi) : "l"(a3));
            a3l = __uint_as_float(lo); a3h = __uint_as_float(hi);
        }
        {
            int r0 = rg * 4, b0 = cg * 2;
            *(float2*)(zbuf + (r0 + 0) * NB + b0) = make_float2(a0l, a2l);
            *(float2*)(zbuf + (r0 + 1) * NB + b0) = make_float2(a0h, a2h);
            *(float2*)(zbuf + (r0 + 2) * NB + b0) = make_float2(a1l, a3l);
            *(float2*)(zbuf + (r0 + 3) * NB + b0) = make_float2(a1h, a3h);
        }

        // barrier #1: z staged locally; cluster-wide everyone finished READING h
        CLUSTER_SYNC();

        // now safe to overwrite our x rows with the next timestep
        if (pf) {
            *(float4*)(cbuf + prow * NB + pq)     = p0;
            *(float4*)(cbuf + prow * NB + pq + 4) = p1;
        }

        // ---- epilogue: thread owns hidden unit hg, batches (bg+b0, bg+b0+1) ----
        {
            const int j = rg, b0 = cg * 2;
            float2 zF = *(float2*)(zbuf + (      j) * NB + b0);
            float2 zI = *(float2*)(zbuf + ( 32 + j) * NB + b0);
            float2 zC = *(float2*)(zbuf + ( 64 + j) * NB + b0);
            float2 zO = *(float2*)(zbuf + ( 96 + j) * NB + b0);

            float f0 = sigm(zF.x + bsf),  f1 = sigm(zF.y + bsf);
            float i0 = sigm(zI.x + bsi),  i1 = sigm(zI.y + bsi);
            float g0 = tanhf_(zC.x + bsc), g1 = tanhf_(zC.y + bsc);
            float o0 = sigm(zO.x + bso),  o1 = sigm(zO.y + bso);

            c0s = f0 * c0s + i0 * g0;
            c1s = f1 * c1s + i1 * g1;
            float h0 = o0 * tanhf_(c0s);
            float h1 = o1 * tanhf_(c1s);

            // broadcast h slice to every CTA's concat buffer (DSMEM push)
            if (pf) {
                unsigned long long hp;
                uint32_t hu0 = __float_as_uint(h0), hu1 = __float_as_uint(h1);
                asm("mov.b64 %0,{%1,%2};" : "=l"(hp) : "r"(hu0), "r"(hu1));
                #pragma unroll
                for (int p = 0; p < CL; ++p) {
                    uint32_t ra;
                    asm("mapa.shared::cluster.u32 %0,%1,%2;"
                        : "=r"(ra) : "r"(haddr), "r"(p));
                    asm volatile("st.shared::cluster.b64 [%0],%1;"
                                 :: "r"(ra), "l"(hp) : "memory");
                }
            }

            // output[b, tt, dir*H + hg]
            size_t obase = ((size_t)(bg + b0) * Ssz + (size_t)tt) * (2 * Hsz)
                           + (size_t)dir * Hsz + hg;
            out[obase]                            = h0;
            out[obase + (size_t)Ssz * 2 * Hsz]    = h1;

            if (step == Ssz - 1 && write_states) {
                size_t hb = (size_t)OUT_MAIN
                          + ((size_t)dir * Bsz + bg + b0) * Hsz + hg;
                out[hb]          = h0;
                out[hb + Hsz]    = h1;
                size_t cb = hb + 2 * (size_t)Bsz * Hsz;
                out[cb]          = c0s;
                out[cb + Hsz]    = c1s;
            }
        }

        // barrier #2: all h_next writes visible cluster-wide before next GEMM
        CLUSTER_SYNC();
    }
}

extern "C" void kernel_launch(void* const* d_in, const int* in_sizes, int n_in,
                              void* d_out, int out_size)
{
    const float* x  = (const float*)d_in[0];
    const float* Wf = (const float*)d_in[1];
    const float* bf = (const float*)d_in[2];
    const float* Wb = (const float*)d_in[3];
    const float* bb = (const float*)d_in[4];

    cudaFuncSetAttribute(bilstm_kernel,
                         cudaFuncAttributeMaxDynamicSharedMemorySize, SMEM_BYTES);

    int ws = ((long long)out_size >= OUT_FULL) ? 1 : 0;
    bilstm_kernel<<<128, 256, SMEM_BYTES>>>(x, Wf, bf, Wb, bb, (float*)d_out, ws);
}